// round 2
// baseline (speedup 1.0000x reference)
#include <cuda_runtime.h>

// out[b][e] = sum_n v[b][n][e]
// Reference's softmax is over a size-1 axis => identically 1.0; everything
// except the v-reduction is dead code. Pure HBM-streaming problem: 256 MB read.

#define BSZ 32
#define NQ  2048
#define EMB 1024
#define NCHUNKS 64
#define NPER   (NQ / NCHUNKS)   // 32 rows per block

__global__ void zero_out_kernel(float* __restrict__ out, int n) {
    int i = blockIdx.x * blockDim.x + threadIdx.x;
    if (i < n) out[i] = 0.0f;
}

__global__ __launch_bounds__(256) void vsum_kernel(const float* __restrict__ v,
                                                   float* __restrict__ out) {
    const int b     = blockIdx.x;          // 0..31
    const int chunk = blockIdx.y;          // 0..63
    const int e4    = threadIdx.x;         // 0..255 -> float4 column index

    const float4* vp = reinterpret_cast<const float4*>(
                           v + (size_t)b * NQ * EMB + (size_t)chunk * NPER * EMB) + e4;

    float4 a0 = make_float4(0.f, 0.f, 0.f, 0.f);
    float4 a1 = make_float4(0.f, 0.f, 0.f, 0.f);
    float4 a2 = make_float4(0.f, 0.f, 0.f, 0.f);
    float4 a3 = make_float4(0.f, 0.f, 0.f, 0.f);

    // 32 rows, stride 4 KB. Streaming loads (evict-first) — data is touched
    // exactly once, keep it out of L2's allocate/evict churn. 4 independent
    // accumulator chains; unroll 8 gives 8 loads in flight per window.
    #pragma unroll 8
    for (int n = 0; n < NPER; n += 4) {
        float4 x0 = __ldcs(vp + (size_t)(n + 0) * (EMB / 4));
        float4 x1 = __ldcs(vp + (size_t)(n + 1) * (EMB / 4));
        float4 x2 = __ldcs(vp + (size_t)(n + 2) * (EMB / 4));
        float4 x3 = __ldcs(vp + (size_t)(n + 3) * (EMB / 4));
        a0.x += x0.x; a0.y += x0.y; a0.z += x0.z; a0.w += x0.w;
        a1.x += x1.x; a1.y += x1.y; a1.z += x1.z; a1.w += x1.w;
        a2.x += x2.x; a2.y += x2.y; a2.z += x2.z; a2.w += x2.w;
        a3.x += x3.x; a3.y += x3.y; a3.z += x3.z; a3.w += x3.w;
    }

    float sx = (a0.x + a1.x) + (a2.x + a3.x);
    float sy = (a0.y + a1.y) + (a2.y + a3.y);
    float sz = (a0.z + a1.z) + (a2.z + a3.z);
    float sw = (a0.w + a1.w) + (a2.w + a3.w);

    float* o = out + (size_t)b * EMB + (size_t)e4 * 4;
    atomicAdd(o + 0, sx);
    atomicAdd(o + 1, sy);
    atomicAdd(o + 2, sz);
    atomicAdd(o + 3, sw);
}

extern "C" void kernel_launch(void* const* d_in, const int* in_sizes, int n_in,
                              void* d_out, int out_size) {
    // metadata order: q, k, v, Wq, bq, Wk, bk, Ws, bs
    const float* v = (const float*)d_in[2];
    float* out = (float*)d_out;

    // d_out is poisoned; zero it before accumulation.
    zero_out_kernel<<<(out_size + 255) / 256, 256>>>(out, out_size);

    dim3 grid(BSZ, NCHUNKS);
    vsum_kernel<<<grid, 256>>>(v, out);
}